// round 1
// baseline (speedup 1.0000x reference)
#include <cuda_runtime.h>
#include <math.h>

#define NWIN 16
#define HN 8
#define NQ 196
#define NV 3136
#define DM 256
#define QKD 128
#define DK 16
#define DV 32
#define PE 729
#define BN_EPS 1e-5f

// Scratch (allocation-free)
__device__ float g_qk[NWIN * DM * NQ];      // conv-bn output of x (q then k channels)
__device__ float g_vv[DM * NV];             // conv-bn output of v_in
__device__ float g_A [NWIN * HN * NQ * NQ]; // per-window softmax attention
__device__ float g_W [NWIN * HN * NQ * DV]; // per-window A@V
__device__ float g_cag[HN * 784 * 16];      // gathered ca modulation C[h][p][m]
__device__ float g_pre[NV * DM];            // pre-FC features

// ---------------------------------------------------------------------------
// 1x1 conv + BN as tiled GEMM: out[b][o][p] = (sum_c w[o][c]*x[b][c][p])*s[o]+t[o]
// ---------------------------------------------------------------------------
__global__ void convbn_kernel(const float* __restrict__ x, const float* __restrict__ w,
                              const float* __restrict__ gamma, const float* __restrict__ beta,
                              const float* __restrict__ mean, const float* __restrict__ var,
                              float* __restrict__ out, int P)
{
    __shared__ float ws[32][33];
    __shared__ float xs[32][33];
    int b  = blockIdx.z;
    int o0 = blockIdx.y * 32;
    int p0 = blockIdx.x * 32;
    const float* xb = x   + (size_t)b * DM * P;
    float*       ob = out + (size_t)b * DM * P;
    int tid = threadIdx.x;
    int tx = tid & 31;    // p within tile
    int to = tid >> 5;    // 0..7, o = o0 + to + j*8
    float acc[4] = {0.f, 0.f, 0.f, 0.f};
    for (int kk = 0; kk < DM; kk += 32) {
        for (int l = tid; l < 1024; l += 256) {
            int r = l >> 5, c = l & 31;
            ws[r][c] = w[(o0 + r) * DM + kk + c];
            int p = p0 + c;
            xs[r][c] = (p < P) ? xb[(size_t)(kk + r) * P + p] : 0.f;
        }
        __syncthreads();
#pragma unroll
        for (int i = 0; i < 32; i++) {
            float xv = xs[i][tx];
#pragma unroll
            for (int j = 0; j < 4; j++)
                acc[j] += ws[to + j * 8][i] * xv;
        }
        __syncthreads();
    }
    int p = p0 + tx;
    if (p < P) {
#pragma unroll
        for (int j = 0; j < 4; j++) {
            int o = o0 + to + j * 8;
            float s = gamma[o] * rsqrtf(var[o] + BN_EPS);
            ob[(size_t)o * P + p] = acc[j] * s + (beta[o] - mean[o] * s);
        }
    }
}

// ---------------------------------------------------------------------------
// scores: A[win,h,q,j] = (q . k)/4 + pos_emb[h][rel_idx[q,j]]
// one block per (win, head); threads own key column j
// ---------------------------------------------------------------------------
__global__ void scores_kernel(const float* __restrict__ pos_emb, const int* __restrict__ rel_idx)
{
    __shared__ float qs[DK * NQ];
    __shared__ float ks[DK * NQ];
    __shared__ float pe[PE];
    int win = blockIdx.x, h = blockIdx.y;
    int tid = threadIdx.x;
    const float* qbase = g_qk + ((size_t)win * DM + h * DK) * NQ;
    const float* kbase = g_qk + ((size_t)win * DM + QKD + h * DK) * NQ;
    for (int l = tid; l < DK * NQ; l += 256) { qs[l] = qbase[l]; ks[l] = kbase[l]; }
    for (int l = tid; l < PE; l += 256) pe[l] = pos_emb[h * PE + l];
    __syncthreads();
    if (tid < NQ) {
        float kc[DK];
#pragma unroll
        for (int d = 0; d < DK; d++) kc[d] = ks[d * NQ + tid];
        float* arow = g_A + ((size_t)(win * HN + h) * NQ) * NQ;
        for (int q = 0; q < NQ; q++) {
            float s = 0.f;
#pragma unroll
            for (int d = 0; d < DK; d++) s += kc[d] * qs[d * NQ + q];
            arow[(size_t)q * NQ + tid] = s * 0.25f + pe[rel_idx[q * NQ + tid]];
        }
    }
}

// ---------------------------------------------------------------------------
// row softmax on g_A, one warp per row of 196
// ---------------------------------------------------------------------------
__global__ void softmax_kernel()
{
    int warp = threadIdx.x >> 5;
    int lane = threadIdx.x & 31;
    int row = blockIdx.x * 4 + warp;
    float* r = g_A + (size_t)row * NQ;
    float v[7];
    float m = -1e30f;
#pragma unroll
    for (int i = 0; i < 7; i++) {
        int j = lane + i * 32;
        v[i] = (j < NQ) ? r[j] : -1e30f;
        m = fmaxf(m, v[i]);
    }
#pragma unroll
    for (int o = 16; o; o >>= 1) m = fmaxf(m, __shfl_xor_sync(~0u, m, o));
    float sum = 0.f;
#pragma unroll
    for (int i = 0; i < 7; i++) {
        v[i] = __expf(v[i] - m);
        if (lane + i * 32 < NQ) sum += v[i];
    }
#pragma unroll
    for (int o = 16; o; o >>= 1) sum += __shfl_xor_sync(~0u, sum, o);
    float inv = __frcp_rn(sum);
#pragma unroll
    for (int i = 0; i < 7; i++) {
        int j = lane + i * 32;
        if (j < NQ) r[j] = v[i] * inv;
    }
}

// ---------------------------------------------------------------------------
// W[win,h,q,d] = sum_k A[win,h,q,k] * V[h, kglobal(win,k), d]
// ---------------------------------------------------------------------------
__global__ void av_kernel()
{
    __shared__ float vs[NQ * DV]; // [kpos*32 + d]
    int win = blockIdx.x, h = blockIdx.y;
    int ki = win >> 2, kj = win & 3;
    int tid = threadIdx.x;
    int vbase = ki * 14 * 56 + kj * 14;
    for (int l = tid; l < NQ * DV; l += 256) {
        int d = l / NQ, kpos = l % NQ;
        int kh = kpos / 14, kw = kpos % 14;
        vs[kpos * DV + d] = g_vv[(size_t)(h * DV + d) * NV + vbase + kh * 56 + kw];
    }
    __syncthreads();
    for (int o = tid; o < NQ * DV; o += 256) {
        int q = o >> 5, d = o & 31;
        const float* arow = g_A + ((size_t)(win * HN + h) * NQ + q) * NQ;
        float acc = 0.f;
#pragma unroll 4
        for (int k = 0; k < NQ; k++) acc += arow[k] * vs[k * DV + d];
        g_W[((size_t)(win * HN + h) * NQ + q) * DV + d] = acc;
    }
}

// ---------------------------------------------------------------------------
// ca gather: C[h,p,m] = ca[h, p, (m/4)*196 + (prow%7)*28 + (m%4)*7 + (pcol%7)]
// (matches reference permute + take_along_axis(ca_index) exactly)
// ---------------------------------------------------------------------------
__global__ void cagather_kernel(const float* __restrict__ ca)
{
    int idx = blockIdx.x * 256 + threadIdx.x;
    if (idx >= HN * 784 * 16) return;
    int m = idx & 15;
    int p = (idx >> 4) % 784;
    int h = idx / (784 * 16);
    int prow = p / 28, pcol = p % 28;
    int orig = (m >> 2) * 196 + (prow % 7) * 28 + (m & 3) * 7 + (pcol % 7);
    g_cag[idx] = ca[((size_t)h * 784 + p) * 784 + orig];
}

// ---------------------------------------------------------------------------
// pre-FC: pre[vq, h*32+d] = sum_m C[h, p(vq), m] * W[m, h, qpos(vq), d]
// ---------------------------------------------------------------------------
__global__ void wsum_kernel()
{
    int vq = blockIdx.x;
    int tid = threadIdx.x;
    int vh = vq / 56, vw = vq % 56;
    int qpos = (vh % 14) * 14 + (vw % 14);
    int p = (vh >> 1) * 28 + (vw >> 1);
    int h = tid >> 5, d = tid & 31;
    const float* cg = g_cag + ((size_t)h * 784 + p) * 16;
    float acc = 0.f;
#pragma unroll
    for (int m = 0; m < 16; m++)
        acc += cg[m] * g_W[((size_t)(m * HN + h) * NQ + qpos) * DV + d];
    g_pre[(size_t)vq * DM + tid] = acc;
}

// ---------------------------------------------------------------------------
// FC: out[q,o] = sum_c pre[q,c]*fc_w[o,c] + fc_b[o]  (NT GEMM, tiled)
// ---------------------------------------------------------------------------
__global__ void fc_kernel(const float* __restrict__ fw, const float* __restrict__ fb,
                          float* __restrict__ out)
{
    __shared__ float ps[32][33];
    __shared__ float ws[32][33];
    int q0 = blockIdx.x * 32;
    int o0 = blockIdx.y * 32;
    int tid = threadIdx.x;
    int tx = tid & 31, ty = tid >> 5;
    float acc[4] = {0.f, 0.f, 0.f, 0.f};
    for (int kk = 0; kk < DM; kk += 32) {
        for (int l = tid; l < 1024; l += 256) {
            int r = l >> 5, c = l & 31;
            ps[r][c] = g_pre[(size_t)(q0 + r) * DM + kk + c];
            ws[r][c] = fw[(o0 + r) * DM + kk + c];
        }
        __syncthreads();
#pragma unroll
        for (int i = 0; i < 32; i++) {
            float wv = ws[tx][i];
#pragma unroll
            for (int j = 0; j < 4; j++) acc[j] += ps[ty * 4 + j][i] * wv;
        }
        __syncthreads();
    }
    float b = fb[o0 + tx];
#pragma unroll
    for (int j = 0; j < 4; j++)
        out[(size_t)(q0 + ty * 4 + j) * DM + o0 + tx] = acc[j] + b;
}

// ---------------------------------------------------------------------------
// final att: att[h, vq, vk] = A[m(vk), h, qpos(vq), kpos(vk)] * C[h, p(vq), m(vk)]
// one block per (qpos, h); A rows loaded once to smem, reused by 16 q-windows
// ---------------------------------------------------------------------------
__global__ void attwrite_kernel(float* __restrict__ att)
{
    __shared__ float As[16 * NQ];
    __shared__ float cs[256];
    int qpos = blockIdx.x, h = blockIdx.y;
    int qh = qpos / 14, qw = qpos % 14;
    int tid = threadIdx.x;
    for (int l = tid; l < 16 * NQ; l += 256) {
        int m = l / NQ, kpos = l % NQ;
        As[l] = g_A[((size_t)(m * HN + h) * NQ + qpos) * NQ + kpos];
    }
    {
        int w = tid >> 4, m = tid & 15;
        int qi = w >> 2, qj = w & 3;
        int vh = qi * 14 + qh, vw = qj * 14 + qw;
        int p = (vh >> 1) * 28 + (vw >> 1);
        cs[tid] = g_cag[((size_t)h * 784 + p) * 16 + m];
    }
    __syncthreads();
#pragma unroll 1
    for (int w = 0; w < 16; w++) {
        int qi = w >> 2, qj = w & 3;
        size_t vq = (size_t)(qi * 14 + qh) * 56 + qj * 14 + qw;
        float* dst = att + ((size_t)h * NV + vq) * NV;
        for (int vk = tid; vk < NV; vk += 256) {
            int khg = vk / 56, kwg = vk % 56;
            int m = (khg / 14) * 4 + (kwg / 14);
            int kpos = (khg % 14) * 14 + (kwg % 14);
            dst[vk] = As[m * NQ + kpos] * cs[w * 16 + m];
        }
    }
}

// ---------------------------------------------------------------------------
extern "C" void kernel_launch(void* const* d_in, const int* in_sizes, int n_in,
                              void* d_out, int out_size)
{
    const float* x    = (const float*)d_in[0];
    const float* v_in = (const float*)d_in[1];
    const float* ca   = (const float*)d_in[2];
    const float* wqk  = (const float*)d_in[3];
    const float* qk_g = (const float*)d_in[4];
    const float* qk_b = (const float*)d_in[5];
    const float* qk_m = (const float*)d_in[6];
    const float* qk_v = (const float*)d_in[7];
    const float* wv   = (const float*)d_in[8];
    const float* v_g  = (const float*)d_in[9];
    const float* v_b  = (const float*)d_in[10];
    const float* v_m  = (const float*)d_in[11];
    const float* v_v  = (const float*)d_in[12];
    const float* fw   = (const float*)d_in[13];
    const float* fb   = (const float*)d_in[14];
    const float* pe   = (const float*)d_in[15];
    const int*   rel  = (const int*)d_in[16];
    (void)in_sizes; (void)n_in; (void)out_size;

    float* out = (float*)d_out;          // (1,56,56,256)   = 802816 floats
    float* att = out + 802816;           // (1,8,3136,3136) = 78675968 floats

    float *p_qk = nullptr, *p_vv = nullptr;
    cudaGetSymbolAddress((void**)&p_qk, g_qk);
    cudaGetSymbolAddress((void**)&p_vv, g_vv);

    convbn_kernel<<<dim3(7, 8, 16), 256>>>(x, wqk, qk_g, qk_b, qk_m, qk_v, p_qk, NQ);
    convbn_kernel<<<dim3(98, 8, 1), 256>>>(v_in, wv, v_g, v_b, v_m, v_v, p_vv, NV);
    scores_kernel<<<dim3(16, 8), 256>>>(pe, rel);
    softmax_kernel<<<NWIN * HN * NQ / 4, 128>>>();
    av_kernel<<<dim3(16, 8), 256>>>();
    cagather_kernel<<<(HN * 784 * 16 + 255) / 256, 256>>>(ca);
    wsum_kernel<<<NV, 256>>>();
    fc_kernel<<<dim3(98, 8), 256>>>(fw, fb, out);
    attwrite_kernel<<<dim3(196, 8), 256>>>(att);
}

// round 2
// speedup vs baseline: 1.3087x; 1.3087x over previous
#include <cuda_runtime.h>
#include <math.h>

#define NWIN 16
#define HN 8
#define NQ 196
#define NV 3136
#define DM 256
#define QKD 128
#define DK 16
#define DV 32
#define PE 729
#define BN_EPS 1e-5f

// Scratch (allocation-free)
__device__ float g_qk[NWIN * DM * NQ];      // conv-bn output of x (q then k channels)
__device__ float g_vv[DM * NV];             // conv-bn output of v_in
__device__ float g_A [NWIN * HN * NQ * NQ]; // per-window softmax attention
__device__ float g_W [NWIN * HN * NQ * DV]; // per-window A@V
__device__ float g_cag[HN * 784 * 16];      // gathered ca modulation C[h][p][m]
__device__ float g_pre[NV * DM];            // pre-FC features
__device__ int   g_pidx[NV];                // vk -> m*8*38416 + kpos (A-gather offsets)
__device__ int   g_sidx[NV / 4];            // f  -> byte offset into SR[w] for scale float4

// ---------------------------------------------------------------------------
// init: constant index tables for attwrite
// ---------------------------------------------------------------------------
__global__ void init_idx_kernel()
{
    int i = blockIdx.x * 512 + threadIdx.x;
    if (i < NV) {
        int khg = i / 56, kwg = i % 56;
        int mi = khg / 14, kh = khg % 14;
        int mj = kwg / 14, kw = kwg % 14;
        int m = mi * 4 + mj;
        int kpos = kh * 14 + kw;
        g_pidx[i] = m * 8 * 38416 + kpos;
    }
    if (i < NV / 4) {
        int mi = i / 196;          // khg/14 with khg=i/14
        int c  = i % 14;           // float4 column within 56-wide row
        g_sidx[i] = mi * 224 + c * 16;  // byte offset: SR[mi][4c]
    }
}

// ---------------------------------------------------------------------------
// 1x1 conv + BN as tiled GEMM: out[b][o][p] = (sum_c w[o][c]*x[b][c][p])*s[o]+t[o]
// ---------------------------------------------------------------------------
__global__ void convbn_kernel(const float* __restrict__ x, const float* __restrict__ w,
                              const float* __restrict__ gamma, const float* __restrict__ beta,
                              const float* __restrict__ mean, const float* __restrict__ var,
                              float* __restrict__ out, int P)
{
    __shared__ float ws[32][33];
    __shared__ float xs[32][33];
    int b  = blockIdx.z;
    int o0 = blockIdx.y * 32;
    int p0 = blockIdx.x * 32;
    const float* xb = x   + (size_t)b * DM * P;
    float*       ob = out + (size_t)b * DM * P;
    int tid = threadIdx.x;
    int tx = tid & 31;
    int to = tid >> 5;
    float acc[4] = {0.f, 0.f, 0.f, 0.f};
    for (int kk = 0; kk < DM; kk += 32) {
        for (int l = tid; l < 1024; l += 256) {
            int r = l >> 5, c = l & 31;
            ws[r][c] = w[(o0 + r) * DM + kk + c];
            int p = p0 + c;
            xs[r][c] = (p < P) ? xb[(size_t)(kk + r) * P + p] : 0.f;
        }
        __syncthreads();
#pragma unroll
        for (int i = 0; i < 32; i++) {
            float xv = xs[i][tx];
#pragma unroll
            for (int j = 0; j < 4; j++)
                acc[j] += ws[to + j * 8][i] * xv;
        }
        __syncthreads();
    }
    int p = p0 + tx;
    if (p < P) {
#pragma unroll
        for (int j = 0; j < 4; j++) {
            int o = o0 + to + j * 8;
            float s = gamma[o] * rsqrtf(var[o] + BN_EPS);
            ob[(size_t)o * P + p] = acc[j] * s + (beta[o] - mean[o] * s);
        }
    }
}

// ---------------------------------------------------------------------------
// scores: A[win,h,q,j] = (q . k)/4 + pos_emb[h][rel_idx[q,j]]
// ---------------------------------------------------------------------------
__global__ void scores_kernel(const float* __restrict__ pos_emb, const int* __restrict__ rel_idx)
{
    __shared__ float qs[DK * NQ];
    __shared__ float ks[DK * NQ];
    __shared__ float pe[PE];
    int win = blockIdx.x, h = blockIdx.y;
    int tid = threadIdx.x;
    const float* qbase = g_qk + ((size_t)win * DM + h * DK) * NQ;
    const float* kbase = g_qk + ((size_t)win * DM + QKD + h * DK) * NQ;
    for (int l = tid; l < DK * NQ; l += 256) { qs[l] = qbase[l]; ks[l] = kbase[l]; }
    for (int l = tid; l < PE; l += 256) pe[l] = pos_emb[h * PE + l];
    __syncthreads();
    if (tid < NQ) {
        float kc[DK];
#pragma unroll
        for (int d = 0; d < DK; d++) kc[d] = ks[d * NQ + tid];
        float* arow = g_A + ((size_t)(win * HN + h) * NQ) * NQ;
        for (int q = 0; q < NQ; q++) {
            float s = 0.f;
#pragma unroll
            for (int d = 0; d < DK; d++) s += kc[d] * qs[d * NQ + q];
            arow[(size_t)q * NQ + tid] = s * 0.25f + pe[rel_idx[q * NQ + tid]];
        }
    }
}

// ---------------------------------------------------------------------------
// row softmax on g_A, one warp per row of 196
// ---------------------------------------------------------------------------
__global__ void softmax_kernel()
{
    int warp = threadIdx.x >> 5;
    int lane = threadIdx.x & 31;
    int row = blockIdx.x * 4 + warp;
    float* r = g_A + (size_t)row * NQ;
    float v[7];
    float m = -1e30f;
#pragma unroll
    for (int i = 0; i < 7; i++) {
        int j = lane + i * 32;
        v[i] = (j < NQ) ? r[j] : -1e30f;
        m = fmaxf(m, v[i]);
    }
#pragma unroll
    for (int o = 16; o; o >>= 1) m = fmaxf(m, __shfl_xor_sync(~0u, m, o));
    float sum = 0.f;
#pragma unroll
    for (int i = 0; i < 7; i++) {
        v[i] = __expf(v[i] - m);
        if (lane + i * 32 < NQ) sum += v[i];
    }
#pragma unroll
    for (int o = 16; o; o >>= 1) sum += __shfl_xor_sync(~0u, sum, o);
    float inv = __frcp_rn(sum);
#pragma unroll
    for (int i = 0; i < 7; i++) {
        int j = lane + i * 32;
        if (j < NQ) r[j] = v[i] * inv;
    }
}

// ---------------------------------------------------------------------------
// W[win,h,q,d] = sum_k A[win,h,q,k] * V[h, kglobal(win,k), d]
// ---------------------------------------------------------------------------
__global__ void av_kernel()
{
    __shared__ float vs[NQ * DV];
    int win = blockIdx.x, h = blockIdx.y;
    int ki = win >> 2, kj = win & 3;
    int tid = threadIdx.x;
    int vbase = ki * 14 * 56 + kj * 14;
    for (int l = tid; l < NQ * DV; l += 256) {
        int d = l / NQ, kpos = l % NQ;
        int kh = kpos / 14, kw = kpos % 14;
        vs[kpos * DV + d] = g_vv[(size_t)(h * DV + d) * NV + vbase + kh * 56 + kw];
    }
    __syncthreads();
    for (int o = tid; o < NQ * DV; o += 256) {
        int q = o >> 5, d = o & 31;
        const float* arow = g_A + ((size_t)(win * HN + h) * NQ + q) * NQ;
        float acc = 0.f;
#pragma unroll 4
        for (int k = 0; k < NQ; k++) acc += arow[k] * vs[k * DV + d];
        g_W[((size_t)(win * HN + h) * NQ + q) * DV + d] = acc;
    }
}

// ---------------------------------------------------------------------------
// ca gather
// ---------------------------------------------------------------------------
__global__ void cagather_kernel(const float* __restrict__ ca)
{
    int idx = blockIdx.x * 256 + threadIdx.x;
    if (idx >= HN * 784 * 16) return;
    int m = idx & 15;
    int p = (idx >> 4) % 784;
    int h = idx / (784 * 16);
    int prow = p / 28, pcol = p % 28;
    int orig = (m >> 2) * 196 + (prow % 7) * 28 + (m & 3) * 7 + (pcol % 7);
    g_cag[idx] = ca[((size_t)h * 784 + p) * 784 + orig];
}

// ---------------------------------------------------------------------------
// pre-FC
// ---------------------------------------------------------------------------
__global__ void wsum_kernel()
{
    int vq = blockIdx.x;
    int tid = threadIdx.x;
    int vh = vq / 56, vw = vq % 56;
    int qpos = (vh % 14) * 14 + (vw % 14);
    int p = (vh >> 1) * 28 + (vw >> 1);
    int h = tid >> 5, d = tid & 31;
    const float* cg = g_cag + ((size_t)h * 784 + p) * 16;
    float acc = 0.f;
#pragma unroll
    for (int m = 0; m < 16; m++)
        acc += cg[m] * g_W[((size_t)(m * HN + h) * NQ + qpos) * DV + d];
    g_pre[(size_t)vq * DM + tid] = acc;
}

// ---------------------------------------------------------------------------
// FC GEMM
// ---------------------------------------------------------------------------
__global__ void fc_kernel(const float* __restrict__ fw, const float* __restrict__ fb,
                          float* __restrict__ out)
{
    __shared__ float ps[32][33];
    __shared__ float ws[32][33];
    int q0 = blockIdx.x * 32;
    int o0 = blockIdx.y * 32;
    int tid = threadIdx.x;
    int tx = tid & 31, ty = tid >> 5;
    float acc[4] = {0.f, 0.f, 0.f, 0.f};
    for (int kk = 0; kk < DM; kk += 32) {
        for (int l = tid; l < 1024; l += 256) {
            int r = l >> 5, c = l & 31;
            ps[r][c] = g_pre[(size_t)(q0 + r) * DM + kk + c];
            ws[r][c] = fw[(o0 + r) * DM + kk + c];
        }
        __syncthreads();
#pragma unroll
        for (int i = 0; i < 32; i++) {
            float wv = ws[tx][i];
#pragma unroll
            for (int j = 0; j < 4; j++) acc[j] += ps[ty * 4 + j][i] * wv;
        }
        __syncthreads();
    }
    float b = fb[o0 + tx];
#pragma unroll
    for (int j = 0; j < 4; j++)
        out[(size_t)(q0 + ty * 4 + j) * DM + o0 + tx] = acc[j] + b;
}

// ---------------------------------------------------------------------------
// final att writer, v2: ~1.1 instr/element.
// att[h, vq, vk] = A[m(vk), h, qpos(vq), kpos(vk)] * C[h, p(vq), m(vk)]
// Block (qpos, h): P[vk] = permuted A (built via g_pidx), SR[w][mi][col] =
// expanded scales. Main loop: per float4 f, per window w: LDS.128 + 2x f32x2
// mul + streaming STG.128 with compile-time address immediates.
// ---------------------------------------------------------------------------
__global__ void attwrite2_kernel(float* __restrict__ att)
{
    __shared__ __align__(16) float P[NV];         // 12544 B
    __shared__ __align__(16) float SR[16 * 224];  // 14336 B  (w, mi, col)
    __shared__ float cs[256];
    int qpos = blockIdx.x, h = blockIdx.y;
    int qh = qpos / 14, qw = qpos % 14;
    int tid = threadIdx.x;

    // cs[w*16+m] = gathered ca scale for this (h, qpos)
    {
        int w = tid >> 4, m = tid & 15;
        int qi = w >> 2, qj = w & 3;
        int vh = qi * 14 + qh, vw = qj * 14 + qw;
        int p = (vh >> 1) * 28 + (vw >> 1);
        cs[tid] = g_cag[((size_t)h * 784 + p) * 16 + m];
    }
    // P[vk] = A[m(vk)][kpos(vk)] for this (h,qpos), via constant gather table
    {
        const float* arow = g_A + (size_t)h * 38416 + (size_t)qpos * 196;
        for (int vk = tid; vk < NV; vk += 256)
            P[vk] = arow[__ldg(&g_pidx[vk])];
    }
    __syncthreads();
    // SR[w][mi][col] = cs[w*16 + mi*4 + col/14]
    for (int i = tid; i < 16 * 224; i += 256) {
        int w = i / 224, r = i % 224;
        int mi = r / 56, col = r % 56;
        SR[i] = cs[w * 16 + mi * 4 + col / 14];
    }
    __syncthreads();

    char* base = (char*)(att + ((size_t)h * NV + (size_t)(qh * 56 + qw)) * NV);
    char* bq[4];
#pragma unroll
    for (int qi = 0; qi < 4; qi++) bq[qi] = base + (size_t)qi * 9834496;  // qi*784*3136*4

    for (int f = tid; f < NV / 4; f += 256) {
        const ulonglong2 pv = *(const ulonglong2*)(P + 4 * f);
        int sb = __ldg(&g_sidx[f]);                 // byte offset of scale float4
        const char* srb = (const char*)SR + sb;
        int coloff = f * 16;                        // byte offset of vk within row
#pragma unroll
        for (int w = 0; w < 16; w++) {
            ulonglong2 sv = *(const ulonglong2*)(srb + w * 896);
            unsigned long long r0, r1;
            asm("mul.rn.f32x2 %0, %1, %2;" : "=l"(r0) : "l"(pv.x), "l"(sv.x));
            asm("mul.rn.f32x2 %0, %1, %2;" : "=l"(r1) : "l"(pv.y), "l"(sv.y));
            char* dst = bq[w >> 2] + ((w & 3) * 175616 + coloff);  // qj*14*3136*4
            asm volatile("st.global.cs.v2.u64 [%0], {%1, %2};"
                         :: "l"(dst), "l"(r0), "l"(r1) : "memory");
        }
    }
}

// ---------------------------------------------------------------------------
extern "C" void kernel_launch(void* const* d_in, const int* in_sizes, int n_in,
                              void* d_out, int out_size)
{
    const float* x    = (const float*)d_in[0];
    const float* v_in = (const float*)d_in[1];
    const float* ca   = (const float*)d_in[2];
    const float* wqk  = (const float*)d_in[3];
    const float* qk_g = (const float*)d_in[4];
    const float* qk_b = (const float*)d_in[5];
    const float* qk_m = (const float*)d_in[6];
    const float* qk_v = (const float*)d_in[7];
    const float* wv   = (const float*)d_in[8];
    const float* v_g  = (const float*)d_in[9];
    const float* v_b  = (const float*)d_in[10];
    const float* v_m  = (const float*)d_in[11];
    const float* v_v  = (const float*)d_in[12];
    const float* fw   = (const float*)d_in[13];
    const float* fb   = (const float*)d_in[14];
    const float* pe   = (const float*)d_in[15];
    const int*   rel  = (const int*)d_in[16];
    (void)in_sizes; (void)n_in; (void)out_size;

    float* out = (float*)d_out;          // (1,56,56,256)   = 802816 floats
    float* att = out + 802816;           // (1,8,3136,3136) = 78675968 floats

    float *p_qk = nullptr, *p_vv = nullptr;
    cudaGetSymbolAddress((void**)&p_qk, g_qk);
    cudaGetSymbolAddress((void**)&p_vv, g_vv);

    init_idx_kernel<<<(NV + 511) / 512, 512>>>();
    convbn_kernel<<<dim3(7, 8, 16), 256>>>(x, wqk, qk_g, qk_b, qk_m, qk_v, p_qk, NQ);
    convbn_kernel<<<dim3(98, 8, 1), 256>>>(v_in, wv, v_g, v_b, v_m, v_v, p_vv, NV);
    scores_kernel<<<dim3(16, 8), 256>>>(pe, rel);
    softmax_kernel<<<NWIN * HN * NQ / 4, 128>>>();
    av_kernel<<<dim3(16, 8), 256>>>();
    cagather_kernel<<<(HN * 784 * 16 + 255) / 256, 256>>>(ca);
    wsum_kernel<<<NV, 256>>>();
    fc_kernel<<<dim3(98, 8), 256>>>(fw, fb, out);
    attwrite2_kernel<<<dim3(196, 8), 256>>>(att);
}

// round 3
// speedup vs baseline: 1.6354x; 1.2496x over previous
#include <cuda_runtime.h>
#include <math.h>

#define NWIN 16
#define HN 8
#define NQ 196
#define NV 3136
#define DM 256
#define QKD 128
#define DK 16
#define DV 32
#define PE 729
#define BN_EPS 1e-5f

// Scratch (allocation-free)
__device__ float g_qk[NWIN * DM * NQ];      // conv-bn output of x (q then k channels)
__device__ float g_vv[DM * NV];             // conv-bn output of v_in
__device__ float g_A [NWIN * HN * NQ * NQ]; // per-window softmax attention
__device__ float g_W [NWIN * HN * NQ * DV]; // per-window A@V
__device__ float g_cag[HN * 784 * 16];      // gathered ca modulation C[h][p][m]
__device__ float g_pre[NV * DM];            // pre-FC features
__device__ float g_bias[HN * NQ * NQ];      // pe[h][rel_idx[q][j]] pre-gathered
__device__ int   g_pidx[NV];                // vk -> m*8*38416 + kpos (A-gather offsets)
__device__ int   g_sidx[NV / 4];            // f  -> byte offset into SR[w] for scale float4

// ---------------------------------------------------------------------------
// init: constant index tables for attwrite
// ---------------------------------------------------------------------------
__global__ void init_idx_kernel()
{
    int i = blockIdx.x * 512 + threadIdx.x;
    if (i < NV) {
        int khg = i / 56, kwg = i % 56;
        int mi = khg / 14, kh = khg % 14;
        int mj = kwg / 14, kw = kwg % 14;
        int m = mi * 4 + mj;
        int kpos = kh * 14 + kw;
        g_pidx[i] = m * 8 * 38416 + kpos;
    }
    if (i < NV / 4) {
        int mi = i / 196;
        int c  = i % 14;
        g_sidx[i] = mi * 224 + c * 16;
    }
}

// ---------------------------------------------------------------------------
// bias precompute: g_bias[h][q*196+j] = pe[h][rel_idx[q*196+j]]
// ---------------------------------------------------------------------------
__global__ void bias_kernel(const float* __restrict__ pe, const int* __restrict__ rel)
{
    int idx = blockIdx.x * 256 + threadIdx.x;
    if (idx >= HN * NQ * NQ) return;
    int h = idx / (NQ * NQ);
    int r = idx % (NQ * NQ);
    g_bias[idx] = pe[h * PE + __ldg(&rel[r])];
}

// ---------------------------------------------------------------------------
// 1x1 conv + BN as tiled GEMM
// ---------------------------------------------------------------------------
__global__ void convbn_kernel(const float* __restrict__ x, const float* __restrict__ w,
                              const float* __restrict__ gamma, const float* __restrict__ beta,
                              const float* __restrict__ mean, const float* __restrict__ var,
                              float* __restrict__ out, int P)
{
    __shared__ float ws[32][33];
    __shared__ float xs[32][33];
    int b  = blockIdx.z;
    int o0 = blockIdx.y * 32;
    int p0 = blockIdx.x * 32;
    const float* xb = x   + (size_t)b * DM * P;
    float*       ob = out + (size_t)b * DM * P;
    int tid = threadIdx.x;
    int tx = tid & 31;
    int to = tid >> 5;
    float acc[4] = {0.f, 0.f, 0.f, 0.f};
    for (int kk = 0; kk < DM; kk += 32) {
        for (int l = tid; l < 1024; l += 256) {
            int r = l >> 5, c = l & 31;
            ws[r][c] = w[(o0 + r) * DM + kk + c];
            int p = p0 + c;
            xs[r][c] = (p < P) ? xb[(size_t)(kk + r) * P + p] : 0.f;
        }
        __syncthreads();
#pragma unroll
        for (int i = 0; i < 32; i++) {
            float xv = xs[i][tx];
#pragma unroll
            for (int j = 0; j < 4; j++)
                acc[j] += ws[to + j * 8][i] * xv;
        }
        __syncthreads();
    }
    int p = p0 + tx;
    if (p < P) {
#pragma unroll
        for (int j = 0; j < 4; j++) {
            int o = o0 + to + j * 8;
            float s = gamma[o] * rsqrtf(var[o] + BN_EPS);
            ob[(size_t)o * P + p] = acc[j] * s + (beta[o] - mean[o] * s);
        }
    }
}

// ---------------------------------------------------------------------------
// fused scores + softmax: block=(win,h), warp per q-row, K in registers.
// A[win,h,q,j] = softmax_j( (q.k)/4 + bias[h,q,j] )
// ---------------------------------------------------------------------------
__global__ void scores_softmax_kernel()
{
    __shared__ float qs[DK * NQ];
    __shared__ float ks[DK * NQ];
    int win = blockIdx.x, h = blockIdx.y;
    int tid = threadIdx.x;
    int warp = tid >> 5, lane = tid & 31;
    const float* qbase = g_qk + ((size_t)win * DM + h * DK) * NQ;
    const float* kbase = g_qk + ((size_t)win * DM + QKD + h * DK) * NQ;
    for (int l = tid; l < DK * NQ; l += 256) { qs[l] = qbase[l]; ks[l] = kbase[l]; }
    __syncthreads();

    // lane's 7 key columns held in registers
    float kc[7][DK];
#pragma unroll
    for (int i = 0; i < 7; i++) {
        int j = lane + 32 * i;
        bool ok = (j < NQ);
#pragma unroll
        for (int d = 0; d < DK; d++)
            kc[i][d] = ok ? ks[d * NQ + j] : 0.f;
    }

    const float* bias = g_bias + (size_t)h * NQ * NQ;
    float* Ab = g_A + ((size_t)(win * HN + h) * NQ) * NQ;

    for (int q = warp; q < NQ; q += 8) {
        float qv[DK];
#pragma unroll
        for (int d = 0; d < DK; d++) qv[d] = qs[d * NQ + q];
        float v[7];
#pragma unroll
        for (int i = 0; i < 7; i++) {
            int j = lane + 32 * i;
            float b = (j < NQ) ? __ldg(&bias[q * NQ + j]) : -1e30f;
            float s = 0.f;
#pragma unroll
            for (int d = 0; d < DK; d++) s += kc[i][d] * qv[d];
            v[i] = (j < NQ) ? (s * 0.25f + b) : -1e30f;
        }
        float m = -1e30f;
#pragma unroll
        for (int i = 0; i < 7; i++) m = fmaxf(m, v[i]);
#pragma unroll
        for (int o = 16; o; o >>= 1) m = fmaxf(m, __shfl_xor_sync(~0u, m, o));
        float sum = 0.f;
#pragma unroll
        for (int i = 0; i < 7; i++) {
            v[i] = __expf(v[i] - m);
            if (lane + 32 * i < NQ) sum += v[i];
        }
#pragma unroll
        for (int o = 16; o; o >>= 1) sum += __shfl_xor_sync(~0u, sum, o);
        float inv = __frcp_rn(sum);
#pragma unroll
        for (int i = 0; i < 7; i++) {
            int j = lane + 32 * i;
            if (j < NQ) Ab[(size_t)q * NQ + j] = v[i] * inv;
        }
    }
}

// ---------------------------------------------------------------------------
// W[win,h,q,d] = sum_k A[win,h,q,k] * V[h, kglobal(win,k), d]
// ---------------------------------------------------------------------------
__global__ void av_kernel()
{
    __shared__ float vs[NQ * DV];
    int win = blockIdx.x, h = blockIdx.y;
    int ki = win >> 2, kj = win & 3;
    int tid = threadIdx.x;
    int vbase = ki * 14 * 56 + kj * 14;
    for (int l = tid; l < NQ * DV; l += 256) {
        int d = l / NQ, kpos = l % NQ;
        int kh = kpos / 14, kw = kpos % 14;
        vs[kpos * DV + d] = g_vv[(size_t)(h * DV + d) * NV + vbase + kh * 56 + kw];
    }
    __syncthreads();
    for (int o = tid; o < NQ * DV; o += 256) {
        int q = o >> 5, d = o & 31;
        const float4* arow4 = (const float4*)(g_A + ((size_t)(win * HN + h) * NQ + q) * NQ);
        float acc = 0.f;
#pragma unroll 7
        for (int k4 = 0; k4 < NQ / 4; k4++) {
            float4 a = __ldg(&arow4[k4]);
            int k = k4 * 4;
            acc += a.x * vs[(k + 0) * DV + d];
            acc += a.y * vs[(k + 1) * DV + d];
            acc += a.z * vs[(k + 2) * DV + d];
            acc += a.w * vs[(k + 3) * DV + d];
        }
        g_W[((size_t)(win * HN + h) * NQ + q) * DV + d] = acc;
    }
}

// ---------------------------------------------------------------------------
// ca gather
// ---------------------------------------------------------------------------
__global__ void cagather_kernel(const float* __restrict__ ca)
{
    int idx = blockIdx.x * 256 + threadIdx.x;
    if (idx >= HN * 784 * 16) return;
    int m = idx & 15;
    int p = (idx >> 4) % 784;
    int h = idx / (784 * 16);
    int prow = p / 28, pcol = p % 28;
    int orig = (m >> 2) * 196 + (prow % 7) * 28 + (m & 3) * 7 + (pcol % 7);
    g_cag[idx] = ca[((size_t)h * 784 + p) * 784 + orig];
}

// ---------------------------------------------------------------------------
// pre-FC
// ---------------------------------------------------------------------------
__global__ void wsum_kernel()
{
    int vq = blockIdx.x;
    int tid = threadIdx.x;
    int vh = vq / 56, vw = vq % 56;
    int qpos = (vh % 14) * 14 + (vw % 14);
    int p = (vh >> 1) * 28 + (vw >> 1);
    int h = tid >> 5, d = tid & 31;
    const float* cg = g_cag + ((size_t)h * 784 + p) * 16;
    float acc = 0.f;
#pragma unroll
    for (int m = 0; m < 16; m++)
        acc += cg[m] * g_W[((size_t)(m * HN + h) * NQ + qpos) * DV + d];
    g_pre[(size_t)vq * DM + tid] = acc;
}

// ---------------------------------------------------------------------------
// FC GEMM
// ---------------------------------------------------------------------------
__global__ void fc_kernel(const float* __restrict__ fw, const float* __restrict__ fb,
                          float* __restrict__ out)
{
    __shared__ float ps[32][33];
    __shared__ float ws[32][33];
    int q0 = blockIdx.x * 32;
    int o0 = blockIdx.y * 32;
    int tid = threadIdx.x;
    int tx = tid & 31, ty = tid >> 5;
    float acc[4] = {0.f, 0.f, 0.f, 0.f};
    for (int kk = 0; kk < DM; kk += 32) {
        for (int l = tid; l < 1024; l += 256) {
            int r = l >> 5, c = l & 31;
            ps[r][c] = g_pre[(size_t)(q0 + r) * DM + kk + c];
            ws[r][c] = fw[(o0 + r) * DM + kk + c];
        }
        __syncthreads();
#pragma unroll
        for (int i = 0; i < 32; i++) {
            float wv = ws[tx][i];
#pragma unroll
            for (int j = 0; j < 4; j++) acc[j] += ps[ty * 4 + j][i] * wv;
        }
        __syncthreads();
    }
    float b = fb[o0 + tx];
#pragma unroll
    for (int j = 0; j < 4; j++)
        out[(size_t)(q0 + ty * 4 + j) * DM + o0 + tx] = acc[j] + b;
}

// ---------------------------------------------------------------------------
// final att writer
// ---------------------------------------------------------------------------
__global__ void attwrite2_kernel(float* __restrict__ att)
{
    __shared__ __align__(16) float P[NV];
    __shared__ __align__(16) float SR[16 * 224];
    __shared__ float cs[256];
    int qpos = blockIdx.x, h = blockIdx.y;
    int qh = qpos / 14, qw = qpos % 14;
    int tid = threadIdx.x;

    {
        int w = tid >> 4, m = tid & 15;
        int qi = w >> 2, qj = w & 3;
        int vh = qi * 14 + qh, vw = qj * 14 + qw;
        int p = (vh >> 1) * 28 + (vw >> 1);
        cs[tid] = g_cag[((size_t)h * 784 + p) * 16 + m];
    }
    {
        const float* arow = g_A + (size_t)h * 38416 + (size_t)qpos * 196;
        for (int vk = tid; vk < NV; vk += 256)
            P[vk] = arow[__ldg(&g_pidx[vk])];
    }
    __syncthreads();
    for (int i = tid; i < 16 * 224; i += 256) {
        int w = i / 224, r = i % 224;
        int mi = r / 56, col = r % 56;
        SR[i] = cs[w * 16 + mi * 4 + col / 14];
    }
    __syncthreads();

    char* base = (char*)(att + ((size_t)h * NV + (size_t)(qh * 56 + qw)) * NV);

    for (int f = tid; f < NV / 4; f += 256) {
        const ulonglong2 pv = *(const ulonglong2*)(P + 4 * f);
        int sb = __ldg(&g_sidx[f]);
        const char* srb = (const char*)SR + sb;
        int coloff = f * 16;
        char* r0 = base + coloff;
        char* r1 = r0 + 9834496;       // qi stride = 784*3136*4
        char* r2 = r1 + 9834496;
        char* r3 = r2 + 9834496;
#pragma unroll
        for (int w = 0; w < 16; w++) {
            ulonglong2 sv = *(const ulonglong2*)(srb + w * 896);
            unsigned long long a0, a1;
            asm("mul.rn.f32x2 %0, %1, %2;" : "=l"(a0) : "l"(pv.x), "l"(sv.x));
            asm("mul.rn.f32x2 %0, %1, %2;" : "=l"(a1) : "l"(pv.y), "l"(sv.y));
            char* dst = (w < 4 ? r0 : w < 8 ? r1 : w < 12 ? r2 : r3) + (w & 3) * 175616;
            asm volatile("st.global.cs.v2.u64 [%0], {%1, %2};"
                         :: "l"(dst), "l"(a0), "l"(a1) : "memory");
        }
    }
}

// ---------------------------------------------------------------------------
extern "C" void kernel_launch(void* const* d_in, const int* in_sizes, int n_in,
                              void* d_out, int out_size)
{
    const float* x    = (const float*)d_in[0];
    const float* v_in = (const float*)d_in[1];
    const float* ca   = (const float*)d_in[2];
    const float* wqk  = (const float*)d_in[3];
    const float* qk_g = (const float*)d_in[4];
    const float* qk_b = (const float*)d_in[5];
    const float* qk_m = (const float*)d_in[6];
    const float* qk_v = (const float*)d_in[7];
    const float* wv   = (const float*)d_in[8];
    const float* v_g  = (const float*)d_in[9];
    const float* v_b  = (const float*)d_in[10];
    const float* v_m  = (const float*)d_in[11];
    const float* v_v  = (const float*)d_in[12];
    const float* fw   = (const float*)d_in[13];
    const float* fb   = (const float*)d_in[14];
    const float* pe   = (const float*)d_in[15];
    const int*   rel  = (const int*)d_in[16];
    (void)in_sizes; (void)n_in; (void)out_size;

    float* out = (float*)d_out;          // (1,56,56,256)   = 802816 floats
    float* att = out + 802816;           // (1,8,3136,3136) = 78675968 floats

    float *p_qk = nullptr, *p_vv = nullptr;
    cudaGetSymbolAddress((void**)&p_qk, g_qk);
    cudaGetSymbolAddress((void**)&p_vv, g_vv);

    init_idx_kernel<<<(NV + 511) / 512, 512>>>();
    bias_kernel<<<(HN * NQ * NQ + 255) / 256, 256>>>(pe, rel);
    convbn_kernel<<<dim3(7, 8, 16), 256>>>(x, wqk, qk_g, qk_b, qk_m, qk_v, p_qk, NQ);
    convbn_kernel<<<dim3(98, 8, 1), 256>>>(v_in, wv, v_g, v_b, v_m, v_v, p_vv, NV);
    scores_softmax_kernel<<<dim3(16, 8), 256>>>();
    av_kernel<<<dim3(16, 8), 256>>>();
    cagather_kernel<<<(HN * 784 * 16 + 255) / 256, 256>>>(ca);
    wsum_kernel<<<NV, 256>>>();
    fc_kernel<<<dim3(98, 8), 256>>>(fw, fb, out);
    attwrite2_kernel<<<dim3(196, 8), 256>>>(att);
}

// round 4
// speedup vs baseline: 1.9459x; 1.1898x over previous
#include <cuda_runtime.h>
#include <math.h>

#define NWIN 16
#define HN 8
#define NQ 196
#define NV 3136
#define DM 256
#define QKD 128
#define DK 16
#define DV 32
#define PE 729
#define BN_EPS 1e-5f

// Scratch (allocation-free)
__device__ float g_qk[NWIN * DM * NQ];      // conv-bn output of x (q then k channels)
__device__ float g_vv[DM * NV];             // conv-bn output of v_in
__device__ float g_A [NWIN * HN * NQ * NQ]; // per-window softmax attention
__device__ float g_W [NWIN * HN * NQ * DV]; // per-window A@V
__device__ float g_cag[HN * 784 * 16];      // gathered ca modulation C[h][p][m]
__device__ float g_pre[NV * DM];            // pre-FC features
__device__ float g_bias[HN * NQ * NQ];      // pe[h][rel_idx[q][j]] pre-gathered
__device__ int   g_pidx[NV];                // vk -> m*8*38416 + kpos (A-gather offsets)
__device__ int   g_sidx[NV / 4];            // f  -> byte offset into SR[w] for scale float4

// ---------------------------------------------------------------------------
// init: constant index tables for attwrite
// ---------------------------------------------------------------------------
__global__ void init_idx_kernel()
{
    int i = blockIdx.x * 512 + threadIdx.x;
    if (i < NV) {
        int khg = i / 56, kwg = i % 56;
        int mi = khg / 14, kh = khg % 14;
        int mj = kwg / 14, kw = kwg % 14;
        int m = mi * 4 + mj;
        int kpos = kh * 14 + kw;
        g_pidx[i] = m * 8 * 38416 + kpos;
    }
    if (i < NV / 4) {
        int mi = i / 196;
        int c  = i % 14;
        g_sidx[i] = mi * 224 + c * 16;
    }
}

// ---------------------------------------------------------------------------
// bias precompute: g_bias[h][q*196+j] = pe[h][rel_idx[q*196+j]]
// ---------------------------------------------------------------------------
__global__ void bias_kernel(const float* __restrict__ pe, const int* __restrict__ rel)
{
    int idx = blockIdx.x * 256 + threadIdx.x;
    if (idx >= HN * NQ * NQ) return;
    int h = idx / (NQ * NQ);
    int r = idx % (NQ * NQ);
    g_bias[idx] = pe[h * PE + __ldg(&rel[r])];
}

// ---------------------------------------------------------------------------
// 1x1 conv + BN, 64x64 tile, BK=16, 4x4 register tile / thread (256 thr)
// out[b][o][p] = (sum_c w[o][c]*x[b][c][p])*s[o]+t[o]
// ---------------------------------------------------------------------------
__global__ void convbn2_kernel(const float* __restrict__ x, const float* __restrict__ w,
                               const float* __restrict__ gamma, const float* __restrict__ beta,
                               const float* __restrict__ mean, const float* __restrict__ var,
                               float* __restrict__ out, int P)
{
    __shared__ float ws[16][65];                 // [k][o] padded
    __shared__ __align__(16) float xs[16][64];   // [k][p]
    int b  = blockIdx.z;
    int o0 = blockIdx.y * 64;
    int p0 = blockIdx.x * 64;
    const float* xb = x   + (size_t)b * DM * P;
    float*       ob = out + (size_t)b * DM * P;
    int tid = threadIdx.x;
    int tp = tid & 15, to = tid >> 4;
    int lk = tid & 15, lr = tid >> 4;
    float acc[4][4] = {};

    for (int kk = 0; kk < DM; kk += 16) {
        // weights: transpose-on-load (coalesced global, conflict-free store)
#pragma unroll
        for (int j = 0; j < 4; j++)
            ws[lk][lr + 16 * j] = w[(o0 + lr + 16 * j) * DM + kk + lk];
        // x: already k-major, float4 coalesced
        {
            int p = p0 + 4 * lk;
            float4 v;
            if (p < P) v = *(const float4*)&xb[(size_t)(kk + lr) * P + p];
            else       v = make_float4(0.f, 0.f, 0.f, 0.f);
            *(float4*)&xs[lr][4 * lk] = v;
        }
        __syncthreads();
#pragma unroll
        for (int k = 0; k < 16; k++) {
            float4 xv = *(const float4*)&xs[k][tp * 4];
#pragma unroll
            for (int j = 0; j < 4; j++) {
                float wv = ws[k][to * 4 + j];
                acc[j][0] += wv * xv.x;
                acc[j][1] += wv * xv.y;
                acc[j][2] += wv * xv.z;
                acc[j][3] += wv * xv.w;
            }
        }
        __syncthreads();
    }

    int p = p0 + tp * 4;
    if (p < P) {
#pragma unroll
        for (int j = 0; j < 4; j++) {
            int o = o0 + to * 4 + j;
            float s = gamma[o] * rsqrtf(var[o] + BN_EPS);
            float t = beta[o] - mean[o] * s;
            float4 r;
            r.x = acc[j][0] * s + t;
            r.y = acc[j][1] * s + t;
            r.z = acc[j][2] * s + t;
            r.w = acc[j][3] * s + t;
            *(float4*)&ob[(size_t)o * P + p] = r;
        }
    }
}

// ---------------------------------------------------------------------------
// fused scores + softmax: block=(win,h), warp per q-row, K in registers.
// ---------------------------------------------------------------------------
__global__ void scores_softmax_kernel()
{
    __shared__ float qs[DK * NQ];
    __shared__ float ks[DK * NQ];
    int win = blockIdx.x, h = blockIdx.y;
    int tid = threadIdx.x;
    int warp = tid >> 5, lane = tid & 31;
    const float* qbase = g_qk + ((size_t)win * DM + h * DK) * NQ;
    const float* kbase = g_qk + ((size_t)win * DM + QKD + h * DK) * NQ;
    for (int l = tid; l < DK * NQ; l += 256) { qs[l] = qbase[l]; ks[l] = kbase[l]; }
    __syncthreads();

    float kc[7][DK];
#pragma unroll
    for (int i = 0; i < 7; i++) {
        int j = lane + 32 * i;
        bool ok = (j < NQ);
#pragma unroll
        for (int d = 0; d < DK; d++)
            kc[i][d] = ok ? ks[d * NQ + j] : 0.f;
    }

    const float* bias = g_bias + (size_t)h * NQ * NQ;
    float* Ab = g_A + ((size_t)(win * HN + h) * NQ) * NQ;

    for (int q = warp; q < NQ; q += 8) {
        float qv[DK];
#pragma unroll
        for (int d = 0; d < DK; d++) qv[d] = qs[d * NQ + q];
        float v[7];
#pragma unroll
        for (int i = 0; i < 7; i++) {
            int j = lane + 32 * i;
            float b = (j < NQ) ? __ldg(&bias[q * NQ + j]) : -1e30f;
            float s = 0.f;
#pragma unroll
            for (int d = 0; d < DK; d++) s += kc[i][d] * qv[d];
            v[i] = (j < NQ) ? (s * 0.25f + b) : -1e30f;
        }
        float m = -1e30f;
#pragma unroll
        for (int i = 0; i < 7; i++) m = fmaxf(m, v[i]);
#pragma unroll
        for (int o = 16; o; o >>= 1) m = fmaxf(m, __shfl_xor_sync(~0u, m, o));
        float sum = 0.f;
#pragma unroll
        for (int i = 0; i < 7; i++) {
            v[i] = __expf(v[i] - m);
            if (lane + 32 * i < NQ) sum += v[i];
        }
#pragma unroll
        for (int o = 16; o; o >>= 1) sum += __shfl_xor_sync(~0u, sum, o);
        float inv = __frcp_rn(sum);
#pragma unroll
        for (int i = 0; i < 7; i++) {
            int j = lane + 32 * i;
            if (j < NQ) Ab[(size_t)q * NQ + j] = v[i] * inv;
        }
    }
}

// ---------------------------------------------------------------------------
// W[win,h,q,d] = sum_k A[win,h,q,k] * V[h, kglobal(win,k), d]
// ---------------------------------------------------------------------------
__global__ void av_kernel()
{
    __shared__ float vs[NQ * DV];
    int win = blockIdx.x, h = blockIdx.y;
    int ki = win >> 2, kj = win & 3;
    int tid = threadIdx.x;
    int vbase = ki * 14 * 56 + kj * 14;
    for (int l = tid; l < NQ * DV; l += 256) {
        int d = l / NQ, kpos = l % NQ;
        int kh = kpos / 14, kw = kpos % 14;
        vs[kpos * DV + d] = g_vv[(size_t)(h * DV + d) * NV + vbase + kh * 56 + kw];
    }
    __syncthreads();
    for (int o = tid; o < NQ * DV; o += 256) {
        int q = o >> 5, d = o & 31;
        const float4* arow4 = (const float4*)(g_A + ((size_t)(win * HN + h) * NQ + q) * NQ);
        float acc = 0.f;
#pragma unroll 7
        for (int k4 = 0; k4 < NQ / 4; k4++) {
            float4 a = __ldg(&arow4[k4]);
            int k = k4 * 4;
            acc += a.x * vs[(k + 0) * DV + d];
            acc += a.y * vs[(k + 1) * DV + d];
            acc += a.z * vs[(k + 2) * DV + d];
            acc += a.w * vs[(k + 3) * DV + d];
        }
        g_W[((size_t)(win * HN + h) * NQ + q) * DV + d] = acc;
    }
}

// ---------------------------------------------------------------------------
// ca gather
// ---------------------------------------------------------------------------
__global__ void cagather_kernel(const float* __restrict__ ca)
{
    int idx = blockIdx.x * 256 + threadIdx.x;
    if (idx >= HN * 784 * 16) return;
    int m = idx & 15;
    int p = (idx >> 4) % 784;
    int h = idx / (784 * 16);
    int prow = p / 28, pcol = p % 28;
    int orig = (m >> 2) * 196 + (prow % 7) * 28 + (m & 3) * 7 + (pcol % 7);
    g_cag[idx] = ca[((size_t)h * 784 + p) * 784 + orig];
}

// ---------------------------------------------------------------------------
// pre-FC
// ---------------------------------------------------------------------------
__global__ void wsum_kernel()
{
    int vq = blockIdx.x;
    int tid = threadIdx.x;
    int vh = vq / 56, vw = vq % 56;
    int qpos = (vh % 14) * 14 + (vw % 14);
    int p = (vh >> 1) * 28 + (vw >> 1);
    int h = tid >> 5, d = tid & 31;
    const float* cg = g_cag + ((size_t)h * 784 + p) * 16;
    float acc = 0.f;
#pragma unroll
    for (int m = 0; m < 16; m++)
        acc += cg[m] * g_W[((size_t)(m * HN + h) * NQ + qpos) * DV + d];
    g_pre[(size_t)vq * DM + tid] = acc;
}

// ---------------------------------------------------------------------------
// FC GEMM, 64x64 tile, BK=16, 4x4 / thread. out[q][o] = pre[q][:] . fw[o][:] + fb[o]
// ---------------------------------------------------------------------------
__global__ void fc2_kernel(const float* __restrict__ fw, const float* __restrict__ fb,
                           float* __restrict__ out)
{
    __shared__ float ps[16][65];   // [k][q]
    __shared__ float ws[16][65];   // [k][o]
    int q0 = blockIdx.x * 64;
    int o0 = blockIdx.y * 64;
    int tid = threadIdx.x;
    int tq = tid & 15, to = tid >> 4;
    int lk = tid & 15, lr = tid >> 4;
    float acc[4][4] = {};

    for (int kk = 0; kk < DM; kk += 16) {
#pragma unroll
        for (int j = 0; j < 4; j++) {
            ps[lk][lr + 16 * j] = g_pre[(size_t)(q0 + lr + 16 * j) * DM + kk + lk];
            ws[lk][lr + 16 * j] = fw[(o0 + lr + 16 * j) * DM + kk + lk];
        }
        __syncthreads();
#pragma unroll
        for (int k = 0; k < 16; k++) {
            float a[4], bb[4];
#pragma unroll
            for (int i = 0; i < 4; i++) a[i] = ps[k][tq * 4 + i];
#pragma unroll
            for (int j = 0; j < 4; j++) bb[j] = ws[k][to * 4 + j];
#pragma unroll
            for (int i = 0; i < 4; i++)
#pragma unroll
                for (int j = 0; j < 4; j++)
                    acc[i][j] += a[i] * bb[j];
        }
        __syncthreads();
    }

    float4 bv = *(const float4*)&fb[o0 + to * 4];
#pragma unroll
    for (int i = 0; i < 4; i++) {
        int q = q0 + tq * 4 + i;
        float4 r;
        r.x = acc[i][0] + bv.x;
        r.y = acc[i][1] + bv.y;
        r.z = acc[i][2] + bv.z;
        r.w = acc[i][3] + bv.w;
        *(float4*)&out[(size_t)q * DM + o0 + to * 4] = r;
    }
}

// ---------------------------------------------------------------------------
// final att writer
// ---------------------------------------------------------------------------
__global__ void attwrite2_kernel(float* __restrict__ att)
{
    __shared__ __align__(16) float P[NV];
    __shared__ __align__(16) float SR[16 * 224];
    __shared__ float cs[256];
    int qpos = blockIdx.x, h = blockIdx.y;
    int qh = qpos / 14, qw = qpos % 14;
    int tid = threadIdx.x;

    {
        int w = tid >> 4, m = tid & 15;
        int qi = w >> 2, qj = w & 3;
        int vh = qi * 14 + qh, vw = qj * 14 + qw;
        int p = (vh >> 1) * 28 + (vw >> 1);
        cs[tid] = g_cag[((size_t)h * 784 + p) * 16 + m];
    }
    {
        const float* arow = g_A + (size_t)h * 38416 + (size_t)qpos * 196;
        for (int vk = tid; vk < NV; vk += 256)
            P[vk] = arow[__ldg(&g_pidx[vk])];
    }
    __syncthreads();
    for (int i = tid; i < 16 * 224; i += 256) {
        int w = i / 224, r = i % 224;
        int mi = r / 56, col = r % 56;
        SR[i] = cs[w * 16 + mi * 4 + col / 14];
    }
    __syncthreads();

    char* base = (char*)(att + ((size_t)h * NV + (size_t)(qh * 56 + qw)) * NV);

    for (int f = tid; f < NV / 4; f += 256) {
        const ulonglong2 pv = *(const ulonglong2*)(P + 4 * f);
        int sb = __ldg(&g_sidx[f]);
        const char* srb = (const char*)SR + sb;
        int coloff = f * 16;
        char* r0 = base + coloff;
        char* r1 = r0 + 9834496;       // qi stride = 784*3136*4
        char* r2 = r1 + 9834496;
        char* r3 = r2 + 9834496;
#pragma unroll
        for (int w = 0; w < 16; w++) {
            ulonglong2 sv = *(const ulonglong2*)(srb + w * 896);
            unsigned long long a0, a1;
            asm("mul.rn.f32x2 %0, %1, %2;" : "=l"(a0) : "l"(pv.x), "l"(sv.x));
            asm("mul.rn.f32x2 %0, %1, %2;" : "=l"(a1) : "l"(pv.y), "l"(sv.y));
            char* dst = (w < 4 ? r0 : w < 8 ? r1 : w < 12 ? r2 : r3) + (w & 3) * 175616;
            asm volatile("st.global.cs.v2.u64 [%0], {%1, %2};"
                         :: "l"(dst), "l"(a0), "l"(a1) : "memory");
        }
    }
}

// ---------------------------------------------------------------------------
extern "C" void kernel_launch(void* const* d_in, const int* in_sizes, int n_in,
                              void* d_out, int out_size)
{
    const float* x    = (const float*)d_in[0];
    const float* v_in = (const float*)d_in[1];
    const float* ca   = (const float*)d_in[2];
    const float* wqk  = (const float*)d_in[3];
    const float* qk_g = (const float*)d_in[4];
    const float* qk_b = (const float*)d_in[5];
    const float* qk_m = (const float*)d_in[6];
    const float* qk_v = (const float*)d_in[7];
    const float* wv   = (const float*)d_in[8];
    const float* v_g  = (const float*)d_in[9];
    const float* v_b  = (const float*)d_in[10];
    const float* v_m  = (const float*)d_in[11];
    const float* v_v  = (const float*)d_in[12];
    const float* fw   = (const float*)d_in[13];
    const float* fb   = (const float*)d_in[14];
    const float* pe   = (const float*)d_in[15];
    const int*   rel  = (const int*)d_in[16];
    (void)in_sizes; (void)n_in; (void)out_size;

    float* out = (float*)d_out;          // (1,56,56,256)   = 802816 floats
    float* att = out + 802816;           // (1,8,3136,3136) = 78675968 floats

    float *p_qk = nullptr, *p_vv = nullptr;
    cudaGetSymbolAddress((void**)&p_qk, g_qk);
    cudaGetSymbolAddress((void**)&p_vv, g_vv);

    init_idx_kernel<<<(NV + 511) / 512, 512>>>();
    bias_kernel<<<(HN * NQ * NQ + 255) / 256, 256>>>(pe, rel);
    convbn2_kernel<<<dim3(4, 4, 16), 256>>>(x, wqk, qk_g, qk_b, qk_m, qk_v, p_qk, NQ);
    convbn2_kernel<<<dim3(49, 4, 1), 256>>>(v_in, wv, v_g, v_b, v_m, v_v, p_vv, NV);
    scores_softmax_kernel<<<dim3(16, 8), 256>>>();
    av_kernel<<<dim3(16, 8), 256>>>();
    cagather_kernel<<<(HN * 784 * 16 + 255) / 256, 256>>>(ca);
    wsum_kernel<<<NV, 256>>>();
    fc2_kernel<<<dim3(49, 4), 256>>>(fw, fb, out);
    attwrite2_kernel<<<dim3(196, 8), 256>>>(att);
}